// round 15
// baseline (speedup 1.0000x reference)
#include <cuda_runtime.h>
#include <math.h>

#define BB 32
#define NN 2048
#define MM 2048
#define TPB 128                 // 4 warps per block
#define ROWS_PER_BLK 64         // 2 threads per row (half-M each)
#define BPB (NN / ROWS_PER_BLK) // 32 blocks per batch
#define NBLK (BB * BPB)         // 1024 blocks <= 7/SM * 148 = 1036 co-resident
#define HALF_P (MM / 4)         // 512 float4-pairs per M-half
#define ITERS 5
#define LOG2E 1.4426950408889634f
#define CSHIFT 64.0f            // global log2-domain shift (cancels in softmax ratio)

// Scratch (no allocations allowed). All counters monotonic across graph replays.
__device__ float4   g_T4[BB];           // per-batch transform: (c, s, tx, ty)
__device__ float    g_part[NBLK * 8];   // per-block partial sums
__device__ unsigned g_ctr[BB];          // per-batch arrival counters
__device__ unsigned g_gen[BB];          // per-batch generation counters

__device__ __forceinline__ float ex2(float x) {
    float y;
    asm("ex2.approx.ftz.f32 %0, %1;" : "=f"(y) : "f"(x));
    return y;
}

// ---------------------------------------------------------------------------
// Persistent kernel: ONE launch, 5 ICP iterations in-kernel.
// Shape = proven R12/R14 winner: 1024 blocks x 4 warps, 7 blocks/SM (exactly
// 7 warps/SMSP, quantization-free), 2 lanes/row covering half-M each, merged
// by shfl_xor(16). Target tile loaded to smem ONCE.
// Cross-iteration sync is PER-BATCH only: last-arriving block (monotonic
// counter) composes T_{it+1}, bumps g_gen[b]; the batch's other 31 blocks
// spin on g_gen[b] (tid 0 + __nanosleep), then __ldcg the new T.
// ---------------------------------------------------------------------------
__global__ __launch_bounds__(TPB, 7)
void icp_kernel(const float* __restrict__ source,
                const float* __restrict__ target,
                const float* __restrict__ init,
                float* __restrict__ out) {
    __shared__ float4 smT[MM / 2];   // 16 KB: (tx0, ty0, tx1, ty1) — raw copy
    __shared__ float2 smC[MM / 2];   //  8 KB: (c0, c1), c = -log2e*|t|^2 - CSHIFT
    __shared__ float  red[4][8];
    __shared__ unsigned s_win;

    const int tid  = threadIdx.x;
    const int wid  = tid >> 5;
    const int lane = tid & 31;
    const int b    = blockIdx.x >> 5;
    const int blk  = blockIdx.x & 31;

    // Replay base of this batch's generation counter. Read BEFORE this block's
    // first arrival; the first gen bump of this replay needs all 32 batch
    // blocks to arrive, so this read always sees the pre-replay value.
    unsigned gbase = 0;
    if (tid == 0) gbase = *(volatile unsigned*)&g_gen[b];

    // ---- smem fill (once): verbatim tile copy + per-pair c coefficients ----
    const float4* tg = (const float4*)(target + (size_t)b * MM * 2);
#pragma unroll
    for (int i = 0; i < MM / 2 / TPB; i++) {   // 8 iterations
        int p = tid + i * TPB;
        float4 q = tg[p];                      // tx0, ty0, tx1, ty1
        smT[p] = q;
        smC[p] = make_float2(fmaf(-LOG2E, q.x * q.x + q.y * q.y, -CSHIFT),
                             fmaf(-LOG2E, q.z * q.z + q.w * q.w, -CSHIFT));
    }

    // Row for this thread: warp covers 16 rows; lanes l and l+16 share row.
    const int row   = blk * ROWS_PER_BLK + wid * 16 + (lane & 15);
    const int mbase = (lane >> 4) * HALF_P;      // 0 or 512 (float4 index)
    const float2 s2 = ((const float2*)source)[b * NN + row];

    // Initial transform from init (computed once).
    const float th0 = init[b * 3 + 0];
    float Tc = cosf(th0), Ts = sinf(th0);
    float Tx = init[b * 3 + 1], Ty = init[b * 3 + 2];

    __syncthreads();   // smem tile ready

    for (int it = 0; it < ITERS; it++) {
        if (it > 0) {
            // Gate: wait until this batch's iteration-(it-1) update landed.
            if (tid == 0) {
                while (*(volatile unsigned*)&g_gen[b] - gbase < (unsigned)it)
                    __nanosleep(32);
            }
            __syncthreads();
            __threadfence();                    // acquire
            float4 t4 = __ldcg(&g_T4[b]);       // bypass stale L1
            Tc = t4.x; Ts = t4.y; Tx = t4.z; Ty = t4.w;
        }

        const float stx = Tc * s2.x - Ts * s2.y + Tx;
        const float sty = Ts * s2.x + Tc * s2.y + Ty;
        const float px  = 2.f * LOG2E * stx;
        const float py  = 2.f * LOG2E * sty;

        // ---- mainloop: 512 iters, 2 targets each: 10 FFMA + 2 MUFU + 2 LDS ----
        float s0 = 0.f, s1 = 0.f;
        float ax0 = 0.f, ax1 = 0.f;
        float ay0 = 0.f, ay1 = 0.f;

#pragma unroll 16
        for (int p = 0; p < HALF_P; p++) {
            float4 t = smT[mbase + p];
            float2 c = smC[mbase + p];
            float e0 = ex2(fmaf(px, t.x, fmaf(py, t.y, c.x)));
            float e1 = ex2(fmaf(px, t.z, fmaf(py, t.w, c.y)));
            s0 += e0; ax0 = fmaf(e0, t.x, ax0); ay0 = fmaf(e0, t.y, ay0);
            s1 += e1; ax1 = fmaf(e1, t.z, ax1); ay1 = fmaf(e1, t.w, ay1);
        }

        // Merge the two M-halves of this row (lanes l <-> l^16).
        float sS  = s0 + s1;
        float sAx = ax0 + ax1;
        float sAy = ay0 + ay1;
        sS  += __shfl_xor_sync(0xffffffffu, sS, 16);
        sAx += __shfl_xor_sync(0xffffffffu, sAx, 16);
        sAy += __shfl_xor_sync(0xffffffffu, sAy, 16);

        const float inv = 1.0f / sS;
        const float tcx = sAx * inv;
        const float tcy = sAy * inv;

        // ---- 8-term reduction: each row appears in 2 lanes -> exact x0.5 ----
        float v[8];
        v[0] = stx;       v[1] = sty;
        v[2] = tcx;       v[3] = tcy;
        v[4] = stx * tcx; v[5] = stx * tcy;
        v[6] = sty * tcx; v[7] = sty * tcy;
#pragma unroll
        for (int off = 16; off > 0; off >>= 1)
#pragma unroll
            for (int k = 0; k < 8; k++)
                v[k] += __shfl_down_sync(0xffffffffu, v[k], off);
        if (lane == 0)
#pragma unroll
            for (int k = 0; k < 8; k++) red[wid][k] = v[k] * 0.5f;
        __syncthreads();
        if (tid < 8)
            g_part[(b * BPB + blk) * 8 + tid] =
                (red[0][tid] + red[1][tid]) + (red[2][tid] + red[3][tid]);

        // ---- release partials, elect the per-batch updater (last arrival) ----
        __threadfence();
        __syncthreads();
        if (tid == 0) {
            unsigned a = atomicAdd(&g_ctr[b], 1u) + 1u;   // monotonic
            s_win = ((a & 31u) == 0u) ? 1u : 0u;
        }
        __syncthreads();

        // ---- folded update: winner block's warp 0 composes T_{it+1}.
        //      gen bump AFTER the partial reads = read-release for slot reuse.
        if (s_win && tid < 32) {
            __threadfence();   // acquire after counter observation
            const float4* pp = (const float4*)&g_part[(b * BPB + tid) * 8];
            float4 qa = __ldcg(pp);
            float4 qb = __ldcg(pp + 1);
            float w[8] = {qa.x, qa.y, qa.z, qa.w, qb.x, qb.y, qb.z, qb.w};
#pragma unroll
            for (int off = 16; off > 0; off >>= 1)
#pragma unroll
                for (int k = 0; k < 8; k++)
                    w[k] += __shfl_down_sync(0xffffffffu, w[k], off);

            if (tid == 0) {
                const float inN = 1.0f / (float)NN;
                const float csx = w[0] * inN, csy = w[1] * inN;
                const float ctx = w[2] * inN, cty = w[3] * inN;
                const float H00 = w[4] - w[0] * w[2] * inN;
                const float H01 = w[5] - w[0] * w[3] * inN;
                const float H10 = w[6] - w[1] * w[2] * inN;
                const float H11 = w[7] - w[1] * w[3] * inN;

                // Polar factor of H^T == V U^T of the SVD incl. reflection.
                const float b0 = H00 + H11, b1 = H10 - H01;
                const float c0 = H00 - H11, c1 = H10 + H01;
                const float nb  = b0 * b0 + b1 * b1;
                const float nc2 = c0 * c0 + c1 * c1;

                float R00, R01, R10, R11;
                if (nb >= nc2) {
                    float ih = (nb > 0.f) ? rsqrtf(nb) : 0.f;
                    R00 = b0 * ih;  R01 = b1 * ih;
                    R10 = -b1 * ih; R11 = b0 * ih;
                } else {
                    float ih = (nc2 > 0.f) ? rsqrtf(nc2) : 0.f;
                    R00 = c0 * ih;  R01 = c1 * ih;
                    R10 = c1 * ih;  R11 = -c0 * ih;
                }
                const float tdx = ctx - (R00 * csx + R01 * csy);
                const float tdy = cty - (R10 * csx + R11 * csy);

                // Applied delta rotation = normalize(R00, R10).
                const float nn2 = R00 * R00 + R10 * R10;
                const float inh = (nn2 > 0.f) ? rsqrtf(nn2) : 0.f;
                const float cd = R00 * inh, sd = R10 * inh;

                const float nc  = cd * Tc - sd * Ts;
                const float ns  = sd * Tc + cd * Ts;
                const float ntx = cd * Tx - sd * Ty + tdx;
                const float nty = sd * Tx + cd * Ty + tdy;

                g_T4[b] = make_float4(nc, ns, ntx, nty);
                if (it == ITERS - 1) {
                    out[b * 3 + 0] = atan2f(ns, nc);
                    out[b * 3 + 1] = ntx;
                    out[b * 3 + 2] = nty;
                }
                __threadfence();                 // release T before gen bump
                atomicAdd(&g_gen[b], 1u);
            }
        }
    }
}

// ---------------------------------------------------------------------------
extern "C" void kernel_launch(void* const* d_in, const int* in_sizes, int n_in,
                              void* d_out, int out_size) {
    const float* source = (const float*)d_in[0];
    const float* target = (const float*)d_in[1];
    const float* init   = (const float*)d_in[2];
    float* out = (float*)d_out;

    icp_kernel<<<NBLK, TPB>>>(source, target, init, out);
}

// round 16
// speedup vs baseline: 1.0308x; 1.0308x over previous
#include <cuda_runtime.h>
#include <math.h>

#define BB 32
#define NN 2048
#define MM 2048
#define TPB 128                 // 4 warps per block
#define ROWS_PER_BLK 64         // 2 threads per row (half-M each)
#define BPB (NN / ROWS_PER_BLK) // 32 blocks per batch
#define NBLK (BB * BPB)         // 1024 blocks; 7/SM, 28 warps/SM = 7/SMSP exact
#define HALF_P (MM / 4)         // 512 float4-pairs per M-half
#define LOG2E 1.4426950408889634f
#define CSHIFT 64.0f            // global log2-domain shift (cancels in softmax ratio)

// Scratch (no allocations allowed)
__device__ float    g_T[BB * 4];        // per-batch transform: c, s, tx, ty
__device__ float    g_part[NBLK * 8];   // per-block partial sums
__device__ unsigned g_ctr[BB];          // monotonic per-batch arrival counters

__device__ __forceinline__ float ex2(float x) {
    float y;
    asm("ex2.approx.ftz.f32 %0, %1;" : "=f"(y) : "f"(x));
    return y;
}

// ---------------------------------------------------------------------------
// Single kernel type, 5 launches (stream order = cross-iteration sync; graph
// replay pipelines consecutive launches across the boundary, hiding tails).
// 4 warps/block, 7 blocks/SM -> exactly 7 warps per SMSP (quantization-free).
// Each warp: 16 rows x 2 lanes/row; lanes 0-15 cover M[0,1024), lanes 16-31
// M[1024,2048); halves merged by shfl_xor(16) (bitwise identical both lanes).
// Per element: 2 FFMA (logit) + 3 FFMA/FADD (s,ax,ay) + 1 MUFU — proven
// minimal for this formulation; measured at ~99% of the FFMA issue ceiling.
// Epilogue: last-arriving block per batch does the Kabsch update.
// ---------------------------------------------------------------------------
__global__ __launch_bounds__(TPB, 7)
void iter_kernel(const float* __restrict__ source,
                 const float* __restrict__ target,
                 const float* __restrict__ init,
                 float* __restrict__ out,
                 int it) {
    __shared__ float4 smT[MM / 2];   // 16 KB: (tx0, ty0, tx1, ty1) — raw copy
    __shared__ float2 smC[MM / 2];   //  8 KB: (c0, c1), c = -log2e*|t|^2 - CSHIFT
    __shared__ float  red[4][8];
    __shared__ unsigned s_win;

    const int tid  = threadIdx.x;
    const int wid  = tid >> 5;
    const int lane = tid & 31;
    const int b    = blockIdx.x >> 5;
    const int blk  = blockIdx.x & 31;

    // ---- smem fill: verbatim tile copy + per-pair c coefficients ----
    const float4* tg = (const float4*)(target + (size_t)b * MM * 2);
#pragma unroll
    for (int i = 0; i < MM / 2 / TPB; i++) {   // 8 iterations
        int p = tid + i * TPB;
        float4 q = tg[p];                      // tx0, ty0, tx1, ty1
        smT[p] = q;
        smC[p] = make_float2(fmaf(-LOG2E, q.x * q.x + q.y * q.y, -CSHIFT),
                             fmaf(-LOG2E, q.z * q.z + q.w * q.w, -CSHIFT));
    }

    // ---- transform for this iteration (T_it) ----
    float Tc, Ts, Tx, Ty;
    if (it == 0) {
        float th = init[b * 3 + 0];
        Tc = cosf(th); Ts = sinf(th);
        Tx = init[b * 3 + 1]; Ty = init[b * 3 + 2];
    } else {
        Tc = g_T[b * 4 + 0]; Ts = g_T[b * 4 + 1];
        Tx = g_T[b * 4 + 2]; Ty = g_T[b * 4 + 3];
    }

    // Row for this thread: warp covers 16 rows; lanes l and l+16 share row.
    const int row   = blk * ROWS_PER_BLK + wid * 16 + (lane & 15);
    const int mbase = (lane >> 4) * HALF_P;      // 0 or 512 (float4 index)

    const float2 s2 = ((const float2*)source)[b * NN + row];
    const float stx = Tc * s2.x - Ts * s2.y + Tx;
    const float sty = Ts * s2.x + Tc * s2.y + Ty;
    const float px  = 2.f * LOG2E * stx;
    const float py  = 2.f * LOG2E * sty;

    __syncthreads();

    // ---- mainloop: 512 iters, 2 targets each: 10 FFMA + 2 MUFU + 2 LDS ----
    float s0 = 0.f, s1 = 0.f;
    float ax0 = 0.f, ax1 = 0.f;
    float ay0 = 0.f, ay1 = 0.f;

#pragma unroll 16
    for (int p = 0; p < HALF_P; p++) {
        float4 t = smT[mbase + p];
        float2 c = smC[mbase + p];
        float e0 = ex2(fmaf(px, t.x, fmaf(py, t.y, c.x)));
        float e1 = ex2(fmaf(px, t.z, fmaf(py, t.w, c.y)));
        s0 += e0; ax0 = fmaf(e0, t.x, ax0); ay0 = fmaf(e0, t.y, ay0);
        s1 += e1; ax1 = fmaf(e1, t.z, ax1); ay1 = fmaf(e1, t.w, ay1);
    }

    // Merge the two M-halves of this row (lanes l <-> l^16).
    float sS  = s0 + s1;
    float sAx = ax0 + ax1;
    float sAy = ay0 + ay1;
    sS  += __shfl_xor_sync(0xffffffffu, sS, 16);
    sAx += __shfl_xor_sync(0xffffffffu, sAx, 16);
    sAy += __shfl_xor_sync(0xffffffffu, sAy, 16);

    const float inv = 1.0f / sS;
    const float tcx = sAx * inv;
    const float tcy = sAy * inv;

    // ---- 8-term reduction: each row appears in 2 lanes -> exact x0.5 ----
    float v[8];
    v[0] = stx;       v[1] = sty;
    v[2] = tcx;       v[3] = tcy;
    v[4] = stx * tcx; v[5] = stx * tcy;
    v[6] = sty * tcx; v[7] = sty * tcy;
#pragma unroll
    for (int off = 16; off > 0; off >>= 1)
#pragma unroll
        for (int k = 0; k < 8; k++)
            v[k] += __shfl_down_sync(0xffffffffu, v[k], off);
    if (lane == 0)
#pragma unroll
        for (int k = 0; k < 8; k++) red[wid][k] = v[k] * 0.5f;
    __syncthreads();
    if (tid < 8)
        g_part[(b * BPB + blk) * 8 + tid] =
            (red[0][tid] + red[1][tid]) + (red[2][tid] + red[3][tid]);

    // ---- release partials, elect the per-batch updater (last arrival) ----
    __threadfence();
    __syncthreads();
    if (tid == 0) {
        unsigned a = atomicAdd(&g_ctr[b], 1u) + 1u;   // monotonic across replays
        s_win = ((a & 31u) == 0u) ? 1u : 0u;
    }
    __syncthreads();

    // ---- folded update: winner block's warp 0 composes T_{it+1} ----
    if (s_win && tid < 32) {
        __threadfence();   // acquire: order counter observation before reads
        const float4* pp = (const float4*)&g_part[(b * BPB + tid) * 8];
        float4 qa = __ldcg(pp);         // .cg: bypass possibly-stale L1 line
        float4 qb = __ldcg(pp + 1);
        float w[8] = {qa.x, qa.y, qa.z, qa.w, qb.x, qb.y, qb.z, qb.w};
#pragma unroll
        for (int off = 16; off > 0; off >>= 1)
#pragma unroll
            for (int k = 0; k < 8; k++)
                w[k] += __shfl_down_sync(0xffffffffu, w[k], off);

        if (tid == 0) {
            const float inN = 1.0f / (float)NN;
            const float csx = w[0] * inN, csy = w[1] * inN;
            const float ctx = w[2] * inN, cty = w[3] * inN;
            const float H00 = w[4] - w[0] * w[2] * inN;
            const float H01 = w[5] - w[0] * w[3] * inN;
            const float H10 = w[6] - w[1] * w[2] * inN;
            const float H11 = w[7] - w[1] * w[3] * inN;

            // Polar factor of H^T == V U^T of the SVD incl. reflection case.
            const float b0 = H00 + H11, b1 = H10 - H01;
            const float c0 = H00 - H11, c1 = H10 + H01;
            const float nb  = b0 * b0 + b1 * b1;
            const float nc2 = c0 * c0 + c1 * c1;

            float R00, R01, R10, R11;
            if (nb >= nc2) {
                float ih = (nb > 0.f) ? rsqrtf(nb) : 0.f;
                R00 = b0 * ih;  R01 = b1 * ih;
                R10 = -b1 * ih; R11 = b0 * ih;
            } else {
                float ih = (nc2 > 0.f) ? rsqrtf(nc2) : 0.f;
                R00 = c0 * ih;  R01 = c1 * ih;
                R10 = c1 * ih;  R11 = -c0 * ih;
            }
            const float tdx = ctx - (R00 * csx + R01 * csy);
            const float tdy = cty - (R10 * csx + R11 * csy);

            // Applied delta rotation = normalize(R00, R10) (== vec2mat(atan2)).
            const float nn2 = R00 * R00 + R10 * R10;
            const float inh = (nn2 > 0.f) ? rsqrtf(nn2) : 0.f;
            const float cd = R00 * inh, sd = R10 * inh;

            const float nc  = cd * Tc - sd * Ts;     // old T_it still live
            const float ns  = sd * Tc + cd * Ts;
            const float ntx = cd * Tx - sd * Ty + tdx;
            const float nty = sd * Tx + cd * Ty + tdy;

            g_T[b * 4 + 0] = nc;  g_T[b * 4 + 1] = ns;
            g_T[b * 4 + 2] = ntx; g_T[b * 4 + 3] = nty;

            if (it == 4) {
                out[b * 3 + 0] = atan2f(ns, nc);
                out[b * 3 + 1] = ntx;
                out[b * 3 + 2] = nty;
            }
        }
    }
}

// ---------------------------------------------------------------------------
extern "C" void kernel_launch(void* const* d_in, const int* in_sizes, int n_in,
                              void* d_out, int out_size) {
    const float* source = (const float*)d_in[0];
    const float* target = (const float*)d_in[1];
    const float* init   = (const float*)d_in[2];
    float* out = (float*)d_out;

    for (int it = 0; it < 5; it++)
        iter_kernel<<<NBLK, TPB>>>(source, target, init, out, it);
}